// round 11
// baseline (speedup 1.0000x reference)
#include <cuda_runtime.h>

// Problem dims (fixed by the dataset)
#define B_ 8192
#define T_ 26
#define V_ 23
#define E_ 100
#define H_ 128
#define L_ 64

// -------- device scratch (static allocation: allowed; no cudaMalloc) --------
__device__ float g_table[V_ * 3 * H_];                  // 23 x 384 : emb@Wih^T + bih
__device__ float g_ygru[(long)B_ * T_ * H_];            // 8192*26*128  (~109 MB)
__device__ float g_xg[(long)B_ * T_ * 4 * E_];          // 8192*26*400  (~341 MB)

__device__ __forceinline__ float fsigmoid(float x) {
    return __fdividef(1.0f, 1.0f + __expf(-x));         // saturates correctly at +-inf
}
__device__ __forceinline__ float ftanh(float x) {
    return 1.0f - __fdividef(2.0f, __expf(2.0f * x) + 1.0f);  // safe at +-inf
}

// ============================================================================
// K1: table[v][g] = sum_e emb[v][e]*gru_wih[g][e] + gru_bih[g]
// ============================================================================
__global__ void table_kernel(const float* __restrict__ emb,
                             const float* __restrict__ wih,
                             const float* __restrict__ bih) {
    __shared__ float e_s[E_];
    int v = blockIdx.x;
    if (threadIdx.x < E_) e_s[threadIdx.x] = emb[v * E_ + threadIdx.x];
    __syncthreads();
    int g = threadIdx.x;                 // 0..383
    float acc = bih[g];
    #pragma unroll 4
    for (int e = 0; e < E_; e++) acc += e_s[e] * wih[g * E_ + e];
    g_table[v * 384 + g] = acc;
}

// ============================================================================
// K2: GRU. One block = 64 batch rows, all 26 steps. Whh^T resident in SMEM.
//   prologue: h0 = tanh(z @ fc_z_w^T + fc_z_b)
//   per step: hg = h @ Whh^T ; gates from table[x_in] (bih folded) + bhh
// ============================================================================
#define GRU_WPITCH 385   // 384 gate cols padded by 1 for conflict-free SMEM
#define GRU_SMEM ((128 * GRU_WPITCH + 64 * 128 + 64) * 4)

__global__ void __launch_bounds__(512, 1)
gru_kernel(const float* __restrict__ z, const int* __restrict__ x_in,
           const float* __restrict__ fc_w, const float* __restrict__ fc_b,
           const float* __restrict__ whh, const float* __restrict__ bhh)
{
    extern __shared__ float sm[];
    float* wT   = sm;                         // [128][385] : wT[k][g] = whh[g][k]
    float* h_s  = sm + 128 * GRU_WPITCH;      // [64][128]
    int*   tok_s = (int*)(h_s + 64 * 128);    // [64]

    const int tid = threadIdx.x;
    const int j = tid & 127;                  // gate column 0..127
    const int rowbase = (tid >> 7) * 16;      // 4 row-groups of 16
    const int bbase = blockIdx.x * 64;

    // ---- prologue: h0 (stage fc_z_w^T + z tile into the wT region) ----
    {
        float* fwT = wT;                      // [64][129]
        float* z_s = wT + 64 * 129;           // [64][64]
        for (int idx = tid; idx < 128 * 64; idx += 512) {
            int jj = idx >> 6, kk = idx & 63;
            fwT[kk * 129 + jj] = fc_w[idx];
        }
        for (int idx = tid; idx < 64 * 64; idx += 512) {
            int r = idx >> 6, k = idx & 63;
            z_s[idx] = z[(long)(bbase + r) * 64 + k];
        }
        __syncthreads();
        float acc[16];
        #pragma unroll
        for (int rr = 0; rr < 16; rr++) acc[rr] = 0.f;
        for (int k = 0; k < 64; k++) {
            float w = fwT[k * 129 + j];
            #pragma unroll
            for (int rr = 0; rr < 16; rr++)
                acc[rr] += z_s[(rowbase + rr) * 64 + k] * w;
        }
        float b = fc_b[j];
        #pragma unroll
        for (int rr = 0; rr < 16; rr++)
            h_s[(rowbase + rr) * 128 + j] = ftanh(acc[rr] + b);
        __syncthreads();
    }

    // ---- load Whh transposed (conflict-free with pitch 385) ----
    for (int idx = tid; idx < 384 * 128; idx += 512) {
        int g = idx >> 7, k = idx & 127;
        wT[k * GRU_WPITCH + g] = whh[idx];
    }
    const float br = bhh[j], bz = bhh[128 + j], bn = bhh[256 + j];
    __syncthreads();

    // ---- 26 recurrent steps ----
    for (int t = 0; t < T_; t++) {
        if (tid < 64) tok_s[tid] = x_in[(long)(bbase + tid) * T_ + t];
        __syncthreads();

        float ar[16], az[16], an[16];
        #pragma unroll
        for (int rr = 0; rr < 16; rr++) { ar[rr] = 0.f; az[rr] = 0.f; an[rr] = 0.f; }

        #pragma unroll 2
        for (int k = 0; k < 128; k++) {
            const float* wk = wT + k * GRU_WPITCH;
            float wr = wk[j], wz = wk[128 + j], wn = wk[256 + j];
            #pragma unroll
            for (int rr = 0; rr < 16; rr++) {
                float hv = h_s[(rowbase + rr) * 128 + k];   // warp-broadcast
                ar[rr] += hv * wr; az[rr] += hv * wz; an[rr] += hv * wn;
            }
        }

        float hnew[16];
        #pragma unroll
        for (int rr = 0; rr < 16; rr++) {
            int row = rowbase + rr;
            const float* tb = g_table + tok_s[row] * 384;   // L2-resident table
            float r  = fsigmoid(tb[j]       + ar[rr] + br);
            float zg = fsigmoid(tb[128 + j] + az[rr] + bz);
            float n  = ftanh   (tb[256 + j] + r * (an[rr] + bn));
            float ho = h_s[row * 128 + j];
            hnew[rr] = (1.f - zg) * n + zg * ho;
            g_ygru[((long)(bbase + row) * T_ + t) * 128 + j] = hnew[rr];
        }
        __syncthreads();
        #pragma unroll
        for (int rr = 0; rr < 16; rr++)
            h_s[(rowbase + rr) * 128 + j] = hnew[rr];
        __syncthreads();
    }
}

// ============================================================================
// K3: xg = Y(B*T,128) @ lstm_wih^T(128,400) + (bih + bhh)  — dense GEMM
//   block tile: 64 rows x 400 cols (padded to 416), per-thread 4x13 registers
// ============================================================================
#define XG_WPITCH 417
#define XG_SMEM ((128 * XG_WPITCH + 64 * 64 + 416) * 4)

__global__ void __launch_bounds__(512, 1)
xg_kernel(const float* __restrict__ wih, const float* __restrict__ bih,
          const float* __restrict__ bhh)
{
    extern __shared__ float sm[];
    float* wT  = sm;                          // [128][417]
    float* y_s = sm + 128 * XG_WPITCH;        // [64][64] (k-chunked)
    float* bs  = y_s + 64 * 64;               // [416]

    const int tid = threadIdx.x;
    const int tx = tid & 31;
    const int ty = tid >> 5;                  // 0..15 -> 4 rows each

    for (int idx = tid; idx < 128 * XG_WPITCH; idx += 512) wT[idx] = 0.f;
    if (tid < 416) bs[tid] = (tid < 400) ? (bih[tid] + bhh[tid]) : 0.f;
    __syncthreads();
    for (int idx = tid; idx < 400 * 128; idx += 512) {
        int c = idx >> 7, k = idx & 127;
        wT[k * XG_WPITCH + c] = wih[idx];
    }
    __syncthreads();

    float acc[4][13];
    #pragma unroll
    for (int q = 0; q < 4; q++)
        #pragma unroll
        for (int m = 0; m < 13; m++) acc[q][m] = 0.f;

    const long rbase = (long)blockIdx.x * 64;
    for (int kc = 0; kc < 2; kc++) {
        for (int idx = tid; idx < 64 * 64; idx += 512) {
            int r = idx >> 6, k = idx & 63;
            y_s[idx] = g_ygru[(rbase + r) * 128 + kc * 64 + k];
        }
        __syncthreads();
        #pragma unroll 2
        for (int k = 0; k < 64; k++) {
            const float* wk = wT + (kc * 64 + k) * XG_WPITCH + tx;
            float y0 = y_s[(ty * 4 + 0) * 64 + k];
            float y1 = y_s[(ty * 4 + 1) * 64 + k];
            float y2 = y_s[(ty * 4 + 2) * 64 + k];
            float y3 = y_s[(ty * 4 + 3) * 64 + k];
            #pragma unroll
            for (int m = 0; m < 13; m++) {
                float wv = wk[m * 32];
                acc[0][m] += y0 * wv;
                acc[1][m] += y1 * wv;
                acc[2][m] += y2 * wv;
                acc[3][m] += y3 * wv;
            }
        }
        __syncthreads();
    }
    #pragma unroll
    for (int q = 0; q < 4; q++) {
        long row = rbase + ty * 4 + q;
        #pragma unroll
        for (int m = 0; m < 13; m++) {
            int c = tx + m * 32;
            if (c < 400) g_xg[row * 400 + c] = acc[q][m] + bs[c];
        }
    }
}

// ============================================================================
// K4: LSTM (hidden=100) + fused output projection to logits (V=23).
//   64 rows/block, Whh^T + out_w in SMEM, cell state c in registers.
// ============================================================================
#define LS_WPITCH 401
#define LS_OWP 101
#define LS_SMEM ((100 * LS_WPITCH + 64 * 100 + 23 * LS_OWP + 23 + 1) * 4)

__global__ void __launch_bounds__(416, 1)
lstm_kernel(const float* __restrict__ whh, const float* __restrict__ ow,
            const float* __restrict__ ob, float* __restrict__ out)
{
    extern __shared__ float sm[];
    float* wT   = sm;                          // [100][401] : wT[k][c] = whh[c][k]
    float* h_s  = sm + 100 * LS_WPITCH;        // [64][100]
    float* ow_s = h_s + 64 * 100;              // [23][101]
    float* ob_s = ow_s + 23 * LS_OWP;          // [23]

    const int tid = threadIdx.x;
    const bool act = tid < 400;
    const int j = act ? (tid % 100) : 0;
    const int rowbase = act ? (tid / 100) * 16 : 0;
    const int bbase = blockIdx.x * 64;

    for (int idx = tid; idx < 400 * 100; idx += 416) {
        int c = idx / 100, k = idx - c * 100;
        wT[k * LS_WPITCH + c] = whh[idx];
    }
    for (int idx = tid; idx < 23 * 100; idx += 416) {
        int v = idx / 100, e = idx - v * 100;
        ow_s[v * LS_OWP + e] = ow[idx];
    }
    if (tid < 23) ob_s[tid] = ob[tid];
    for (int idx = tid; idx < 64 * 100; idx += 416) h_s[idx] = 0.f;

    float c_reg[16];
    #pragma unroll
    for (int rr = 0; rr < 16; rr++) c_reg[rr] = 0.f;
    __syncthreads();

    for (int t = 0; t < T_; t++) {
        float hnew[16];
        #pragma unroll
        for (int rr = 0; rr < 16; rr++) hnew[rr] = 0.f;

        if (act) {
            float ai[16], af[16], ag[16], ao[16];
            #pragma unroll
            for (int rr = 0; rr < 16; rr++) { ai[rr] = af[rr] = ag[rr] = ao[rr] = 0.f; }

            #pragma unroll 2
            for (int k = 0; k < 100; k++) {
                const float* wk = wT + k * LS_WPITCH + j;
                float wi = wk[0], wf = wk[100], wg = wk[200], wo = wk[300];
                #pragma unroll
                for (int rr = 0; rr < 16; rr++) {
                    float hv = h_s[(rowbase + rr) * 100 + k];   // warp-broadcast
                    ai[rr] += hv * wi; af[rr] += hv * wf;
                    ag[rr] += hv * wg; ao[rr] += hv * wo;
                }
            }
            #pragma unroll
            for (int rr = 0; rr < 16; rr++) {
                int row = rowbase + rr;
                const float* xg = g_xg + ((long)(bbase + row) * T_ + t) * 400;
                float gi = xg[j]       + ai[rr];
                float gf = xg[100 + j] + af[rr];
                float gg = xg[200 + j] + ag[rr];
                float go = xg[300 + j] + ao[rr];
                c_reg[rr] = fsigmoid(gf) * c_reg[rr] + fsigmoid(gi) * ftanh(gg);
                hnew[rr]  = fsigmoid(go) * ftanh(c_reg[rr]);
            }
        }
        __syncthreads();       // all reads of h_s(t-1) done
        if (act) {
            #pragma unroll
            for (int rr = 0; rr < 16; rr++)
                h_s[(rowbase + rr) * 100 + j] = hnew[rr];
        }
        __syncthreads();       // h_s(t) visible

        // fused logits: out[b,t,v] = h . out_w[v] + out_b[v]
        for (int idx = tid; idx < 64 * V_; idx += 416) {
            int row = idx / V_, v = idx - row * V_;
            float acc = ob_s[v];
            #pragma unroll 4
            for (int e = 0; e < E_; e++)
                acc += h_s[row * 100 + e] * ow_s[v * LS_OWP + e];
            out[((long)(bbase + row) * T_ + t) * V_ + v] = acc;
        }
        __syncthreads();
    }
}

// ============================================================================
// launch
// ============================================================================
extern "C" void kernel_launch(void* const* d_in, const int* in_sizes, int n_in,
                              void* d_out, int out_size) {
    const float* z     = (const float*)d_in[0];
    const int*   x_in  = (const int*)  d_in[1];
    const float* emb   = (const float*)d_in[2];
    const float* fc_w  = (const float*)d_in[3];
    const float* fc_b  = (const float*)d_in[4];
    const float* gwih  = (const float*)d_in[5];
    const float* gwhh  = (const float*)d_in[6];
    const float* gbih  = (const float*)d_in[7];
    const float* gbhh  = (const float*)d_in[8];
    const float* lwih  = (const float*)d_in[9];
    const float* lwhh  = (const float*)d_in[10];
    const float* lbih  = (const float*)d_in[11];
    const float* lbhh  = (const float*)d_in[12];
    const float* out_w = (const float*)d_in[13];
    const float* out_b = (const float*)d_in[14];
    float* out = (float*)d_out;

    cudaFuncSetAttribute(gru_kernel,  cudaFuncAttributeMaxDynamicSharedMemorySize, GRU_SMEM);
    cudaFuncSetAttribute(xg_kernel,   cudaFuncAttributeMaxDynamicSharedMemorySize, XG_SMEM);
    cudaFuncSetAttribute(lstm_kernel, cudaFuncAttributeMaxDynamicSharedMemorySize, LS_SMEM);

    table_kernel<<<V_, 384>>>(emb, gwih, gbih);
    gru_kernel<<<B_ / 64, 512, GRU_SMEM>>>(z, x_in, fc_w, fc_b, gwhh, gbhh);
    xg_kernel<<<(B_ * T_) / 64, 512, XG_SMEM>>>(lwih, lbih, lbhh);
    lstm_kernel<<<B_ / 64, 416, LS_SMEM>>>(lwhh, out_w, out_b, out);
}

// round 12
// speedup vs baseline: 1.0032x; 1.0032x over previous
#include <cuda_runtime.h>

// Problem dims (fixed by the dataset)
#define B_ 8192
#define T_ 26
#define V_ 23
#define E_ 100
#define H_ 128
#define L_ 64

// -------- device scratch (static allocation: allowed; no cudaMalloc) --------
__device__ float g_table[V_ * 3 * H_];                  // 23 x 384 : emb@Wih^T + bih
__device__ float g_ygru[(long)B_ * T_ * H_];            // 8192*26*128  (~109 MB)
__device__ float g_xg[(long)B_ * T_ * 4 * E_];          // 8192*26*400  (~341 MB)

__device__ __forceinline__ float fsigmoid(float x) {
    return __fdividef(1.0f, 1.0f + __expf(-x));         // saturates correctly at +-inf
}
__device__ __forceinline__ float ftanh(float x) {
    return 1.0f - __fdividef(2.0f, __expf(2.0f * x) + 1.0f);  // safe at +-inf
}

// ============================================================================
// K1: table[v][g] = sum_e emb[v][e]*gru_wih[g][e] + gru_bih[g]
// ============================================================================
__global__ void table_kernel(const float* __restrict__ emb,
                             const float* __restrict__ wih,
                             const float* __restrict__ bih) {
    __shared__ float e_s[E_];
    int v = blockIdx.x;
    if (threadIdx.x < E_) e_s[threadIdx.x] = emb[v * E_ + threadIdx.x];
    __syncthreads();
    int g = threadIdx.x;                 // 0..383
    float acc = bih[g];
    #pragma unroll 4
    for (int e = 0; e < E_; e++) acc += e_s[e] * wih[g * E_ + e];
    g_table[v * 384 + g] = acc;
}

// ============================================================================
// K2: GRU. One block = 64 batch rows, all 26 steps. Whh^T resident in SMEM.
//   prologue: h0 = tanh(z @ fc_z_w^T + fc_z_b)
//   per step: hg = h @ Whh^T ; gates from table[x_in] (bih folded) + bhh
// ============================================================================
#define GRU_WPITCH 385   // 384 gate cols padded by 1 for conflict-free SMEM
#define GRU_SMEM ((128 * GRU_WPITCH + 64 * 128 + 64) * 4)

__global__ void __launch_bounds__(512, 1)
gru_kernel(const float* __restrict__ z, const int* __restrict__ x_in,
           const float* __restrict__ fc_w, const float* __restrict__ fc_b,
           const float* __restrict__ whh, const float* __restrict__ bhh)
{
    extern __shared__ float sm[];
    float* wT   = sm;                         // [128][385] : wT[k][g] = whh[g][k]
    float* h_s  = sm + 128 * GRU_WPITCH;      // [64][128]
    int*   tok_s = (int*)(h_s + 64 * 128);    // [64]

    const int tid = threadIdx.x;
    const int j = tid & 127;                  // gate column 0..127
    const int rowbase = (tid >> 7) * 16;      // 4 row-groups of 16
    const int bbase = blockIdx.x * 64;

    // ---- prologue: h0 (stage fc_z_w^T + z tile into the wT region) ----
    {
        float* fwT = wT;                      // [64][129]
        float* z_s = wT + 64 * 129;           // [64][64]
        for (int idx = tid; idx < 128 * 64; idx += 512) {
            int jj = idx >> 6, kk = idx & 63;
            fwT[kk * 129 + jj] = fc_w[idx];
        }
        for (int idx = tid; idx < 64 * 64; idx += 512) {
            int r = idx >> 6, k = idx & 63;
            z_s[idx] = z[(long)(bbase + r) * 64 + k];
        }
        __syncthreads();
        float acc[16];
        #pragma unroll
        for (int rr = 0; rr < 16; rr++) acc[rr] = 0.f;
        for (int k = 0; k < 64; k++) {
            float w = fwT[k * 129 + j];
            #pragma unroll
            for (int rr = 0; rr < 16; rr++)
                acc[rr] += z_s[(rowbase + rr) * 64 + k] * w;
        }
        float b = fc_b[j];
        #pragma unroll
        for (int rr = 0; rr < 16; rr++)
            h_s[(rowbase + rr) * 128 + j] = ftanh(acc[rr] + b);
        __syncthreads();
    }

    // ---- load Whh transposed (conflict-free with pitch 385) ----
    for (int idx = tid; idx < 384 * 128; idx += 512) {
        int g = idx >> 7, k = idx & 127;
        wT[k * GRU_WPITCH + g] = whh[idx];
    }
    const float br = bhh[j], bz = bhh[128 + j], bn = bhh[256 + j];
    __syncthreads();

    // ---- 26 recurrent steps ----
    for (int t = 0; t < T_; t++) {
        if (tid < 64) tok_s[tid] = x_in[(long)(bbase + tid) * T_ + t];
        __syncthreads();

        float ar[16], az[16], an[16];
        #pragma unroll
        for (int rr = 0; rr < 16; rr++) { ar[rr] = 0.f; az[rr] = 0.f; an[rr] = 0.f; }

        #pragma unroll 2
        for (int k = 0; k < 128; k++) {
            const float* wk = wT + k * GRU_WPITCH;
            float wr = wk[j], wz = wk[128 + j], wn = wk[256 + j];
            #pragma unroll
            for (int rr = 0; rr < 16; rr++) {
                float hv = h_s[(rowbase + rr) * 128 + k];   // warp-broadcast
                ar[rr] += hv * wr; az[rr] += hv * wz; an[rr] += hv * wn;
            }
        }

        float hnew[16];
        #pragma unroll
        for (int rr = 0; rr < 16; rr++) {
            int row = rowbase + rr;
            const float* tb = g_table + tok_s[row] * 384;   // L2-resident table
            float r  = fsigmoid(tb[j]       + ar[rr] + br);
            float zg = fsigmoid(tb[128 + j] + az[rr] + bz);
            float n  = ftanh   (tb[256 + j] + r * (an[rr] + bn));
            float ho = h_s[row * 128 + j];
            hnew[rr] = (1.f - zg) * n + zg * ho;
            g_ygru[((long)(bbase + row) * T_ + t) * 128 + j] = hnew[rr];
        }
        __syncthreads();
        #pragma unroll
        for (int rr = 0; rr < 16; rr++)
            h_s[(rowbase + rr) * 128 + j] = hnew[rr];
        __syncthreads();
    }
}

// ============================================================================
// K3: xg = Y(B*T,128) @ lstm_wih^T(128,400) + (bih + bhh)  — dense GEMM
//   block tile: 64 rows x 400 cols (padded to 416), per-thread 4x13 registers
// ============================================================================
#define XG_WPITCH 417
#define XG_SMEM ((128 * XG_WPITCH + 64 * 64 + 416) * 4)

__global__ void __launch_bounds__(512, 1)
xg_kernel(const float* __restrict__ wih, const float* __restrict__ bih,
          const float* __restrict__ bhh)
{
    extern __shared__ float sm[];
    float* wT  = sm;                          // [128][417]
    float* y_s = sm + 128 * XG_WPITCH;        // [64][64] (k-chunked)
    float* bs  = y_s + 64 * 64;               // [416]

    const int tid = threadIdx.x;
    const int tx = tid & 31;
    const int ty = tid >> 5;                  // 0..15 -> 4 rows each

    for (int idx = tid; idx < 128 * XG_WPITCH; idx += 512) wT[idx] = 0.f;
    if (tid < 416) bs[tid] = (tid < 400) ? (bih[tid] + bhh[tid]) : 0.f;
    __syncthreads();
    for (int idx = tid; idx < 400 * 128; idx += 512) {
        int c = idx >> 7, k = idx & 127;
        wT[k * XG_WPITCH + c] = wih[idx];
    }
    __syncthreads();

    float acc[4][13];
    #pragma unroll
    for (int q = 0; q < 4; q++)
        #pragma unroll
        for (int m = 0; m < 13; m++) acc[q][m] = 0.f;

    const long rbase = (long)blockIdx.x * 64;
    for (int kc = 0; kc < 2; kc++) {
        for (int idx = tid; idx < 64 * 64; idx += 512) {
            int r = idx >> 6, k = idx & 63;
            y_s[idx] = g_ygru[(rbase + r) * 128 + kc * 64 + k];
        }
        __syncthreads();
        #pragma unroll 2
        for (int k = 0; k < 64; k++) {
            const float* wk = wT + (kc * 64 + k) * XG_WPITCH + tx;
            float y0 = y_s[(ty * 4 + 0) * 64 + k];
            float y1 = y_s[(ty * 4 + 1) * 64 + k];
            float y2 = y_s[(ty * 4 + 2) * 64 + k];
            float y3 = y_s[(ty * 4 + 3) * 64 + k];
            #pragma unroll
            for (int m = 0; m < 13; m++) {
                float wv = wk[m * 32];
                acc[0][m] += y0 * wv;
                acc[1][m] += y1 * wv;
                acc[2][m] += y2 * wv;
                acc[3][m] += y3 * wv;
            }
        }
        __syncthreads();
    }
    #pragma unroll
    for (int q = 0; q < 4; q++) {
        long row = rbase + ty * 4 + q;
        #pragma unroll
        for (int m = 0; m < 13; m++) {
            int c = tx + m * 32;
            if (c < 400) g_xg[row * 400 + c] = acc[q][m] + bs[c];
        }
    }
}

// ============================================================================
// K4: LSTM (hidden=100) + fused output projection to logits (V=23).
//   64 rows/block, Whh^T + out_w in SMEM, cell state c in registers.
// ============================================================================
#define LS_WPITCH 401
#define LS_OWP 101
#define LS_SMEM ((100 * LS_WPITCH + 64 * 100 + 23 * LS_OWP + 23 + 1) * 4)

__global__ void __launch_bounds__(416, 1)
lstm_kernel(const float* __restrict__ whh, const float* __restrict__ ow,
            const float* __restrict__ ob, float* __restrict__ out)
{
    extern __shared__ float sm[];
    float* wT   = sm;                          // [100][401] : wT[k][c] = whh[c][k]
    float* h_s  = sm + 100 * LS_WPITCH;        // [64][100]
    float* ow_s = h_s + 64 * 100;              // [23][101]
    float* ob_s = ow_s + 23 * LS_OWP;          // [23]

    const int tid = threadIdx.x;
    const bool act = tid < 400;
    const int j = act ? (tid % 100) : 0;
    const int rowbase = act ? (tid / 100) * 16 : 0;
    const int bbase = blockIdx.x * 64;

    for (int idx = tid; idx < 400 * 100; idx += 416) {
        int c = idx / 100, k = idx - c * 100;
        wT[k * LS_WPITCH + c] = whh[idx];
    }
    for (int idx = tid; idx < 23 * 100; idx += 416) {
        int v = idx / 100, e = idx - v * 100;
        ow_s[v * LS_OWP + e] = ow[idx];
    }
    if (tid < 23) ob_s[tid] = ob[tid];
    for (int idx = tid; idx < 64 * 100; idx += 416) h_s[idx] = 0.f;

    float c_reg[16];
    #pragma unroll
    for (int rr = 0; rr < 16; rr++) c_reg[rr] = 0.f;
    __syncthreads();

    for (int t = 0; t < T_; t++) {
        float hnew[16];
        #pragma unroll
        for (int rr = 0; rr < 16; rr++) hnew[rr] = 0.f;

        if (act) {
            float ai[16], af[16], ag[16], ao[16];
            #pragma unroll
            for (int rr = 0; rr < 16; rr++) { ai[rr] = af[rr] = ag[rr] = ao[rr] = 0.f; }

            #pragma unroll 2
            for (int k = 0; k < 100; k++) {
                const float* wk = wT + k * LS_WPITCH + j;
                float wi = wk[0], wf = wk[100], wg = wk[200], wo = wk[300];
                #pragma unroll
                for (int rr = 0; rr < 16; rr++) {
                    float hv = h_s[(rowbase + rr) * 100 + k];   // warp-broadcast
                    ai[rr] += hv * wi; af[rr] += hv * wf;
                    ag[rr] += hv * wg; ao[rr] += hv * wo;
                }
            }
            #pragma unroll
            for (int rr = 0; rr < 16; rr++) {
                int row = rowbase + rr;
                const float* xg = g_xg + ((long)(bbase + row) * T_ + t) * 400;
                float gi = xg[j]       + ai[rr];
                float gf = xg[100 + j] + af[rr];
                float gg = xg[200 + j] + ag[rr];
                float go = xg[300 + j] + ao[rr];
                c_reg[rr] = fsigmoid(gf) * c_reg[rr] + fsigmoid(gi) * ftanh(gg);
                hnew[rr]  = fsigmoid(go) * ftanh(c_reg[rr]);
            }
        }
        __syncthreads();       // all reads of h_s(t-1) done
        if (act) {
            #pragma unroll
            for (int rr = 0; rr < 16; rr++)
                h_s[(rowbase + rr) * 100 + j] = hnew[rr];
        }
        __syncthreads();       // h_s(t) visible

        // fused logits: out[b,t,v] = h . out_w[v] + out_b[v]
        for (int idx = tid; idx < 64 * V_; idx += 416) {
            int row = idx / V_, v = idx - row * V_;
            float acc = ob_s[v];
            #pragma unroll 4
            for (int e = 0; e < E_; e++)
                acc += h_s[row * 100 + e] * ow_s[v * LS_OWP + e];
            out[((long)(bbase + row) * T_ + t) * V_ + v] = acc;
        }
        __syncthreads();
    }
}

// ============================================================================
// launch
// ============================================================================
extern "C" void kernel_launch(void* const* d_in, const int* in_sizes, int n_in,
                              void* d_out, int out_size) {
    const float* z     = (const float*)d_in[0];
    const int*   x_in  = (const int*)  d_in[1];
    const float* emb   = (const float*)d_in[2];
    const float* fc_w  = (const float*)d_in[3];
    const float* fc_b  = (const float*)d_in[4];
    const float* gwih  = (const float*)d_in[5];
    const float* gwhh  = (const float*)d_in[6];
    const float* gbih  = (const float*)d_in[7];
    const float* gbhh  = (const float*)d_in[8];
    const float* lwih  = (const float*)d_in[9];
    const float* lwhh  = (const float*)d_in[10];
    const float* lbih  = (const float*)d_in[11];
    const float* lbhh  = (const float*)d_in[12];
    const float* out_w = (const float*)d_in[13];
    const float* out_b = (const float*)d_in[14];
    float* out = (float*)d_out;

    cudaFuncSetAttribute(gru_kernel,  cudaFuncAttributeMaxDynamicSharedMemorySize, GRU_SMEM);
    cudaFuncSetAttribute(xg_kernel,   cudaFuncAttributeMaxDynamicSharedMemorySize, XG_SMEM);
    cudaFuncSetAttribute(lstm_kernel, cudaFuncAttributeMaxDynamicSharedMemorySize, LS_SMEM);

    table_kernel<<<V_, 384>>>(emb, gwih, gbih);
    gru_kernel<<<B_ / 64, 512, GRU_SMEM>>>(z, x_in, fc_w, fc_b, gwhh, gbhh);
    xg_kernel<<<(B_ * T_) / 64, 512, XG_SMEM>>>(lwih, lbih, lbhh);
    lstm_kernel<<<B_ / 64, 416, LS_SMEM>>>(lwhh, out_w, out_b, out);
}

// round 13
// speedup vs baseline: 1.0398x; 1.0365x over previous
#include <cuda_runtime.h>

// Problem dims (fixed by the dataset)
#define B_ 8192
#define T_ 26
#define V_ 23
#define E_ 100
#define H_ 128
#define L_ 64

typedef unsigned long long u64;

// -------- device scratch (static allocation: allowed; no cudaMalloc) --------
__device__ float g_table[V_ * 3 * H_];                  // 23 x 384 : emb@Wih^T + bih
__device__ float g_ygru[(long)B_ * T_ * H_];            // ~109 MB
__device__ float g_xg[(long)B_ * T_ * 4 * E_];          // ~341 MB

__device__ __forceinline__ float fsigmoid(float x) {
    return __fdividef(1.0f, 1.0f + __expf(-x));
}
__device__ __forceinline__ float ftanh(float x) {
    return 1.0f - __fdividef(2.0f, __expf(2.0f * x) + 1.0f);
}

// ---- packed f32x2 helpers (Blackwell FFMA2 path) ----
__device__ __forceinline__ void ffma2(u64& d, u64 a, u64 b) {
    asm("fma.rn.f32x2 %0, %1, %2, %0;" : "+l"(d) : "l"(a), "l"(b));
}
__device__ __forceinline__ u64 f2_dup(float x) {
    unsigned int u = __float_as_uint(x);
    u64 r; asm("mov.b64 %0, {%1, %1};" : "=l"(r) : "r"(u)); return r;
}
__device__ __forceinline__ u64 f2_make(unsigned int lo, unsigned int hi) {
    u64 r; asm("mov.b64 %0, {%1, %2};" : "=l"(r) : "r"(lo), "r"(hi)); return r;
}
__device__ __forceinline__ void f2_unpack(u64 v, float& lo, float& hi) {
    unsigned int a, b;
    asm("mov.b64 {%0, %1}, %2;" : "=r"(a), "=r"(b) : "l"(v));
    lo = __uint_as_float(a); hi = __uint_as_float(b);
}

// ============================================================================
// K1: table[v][g] = sum_e emb[v][e]*gru_wih[g][e] + gru_bih[g]
// ============================================================================
__global__ void table_kernel(const float* __restrict__ emb,
                             const float* __restrict__ wih,
                             const float* __restrict__ bih) {
    __shared__ float e_s[E_];
    int v = blockIdx.x;
    if (threadIdx.x < E_) e_s[threadIdx.x] = emb[v * E_ + threadIdx.x];
    __syncthreads();
    int g = threadIdx.x;                 // 0..383
    float acc = bih[g];
    #pragma unroll 4
    for (int e = 0; e < E_; e++) acc += e_s[e] * wih[g * E_ + e];
    g_table[v * 384 + g] = acc;
}

// ============================================================================
// K2: GRU, f32x2. One block = 64 rows, all 26 steps. h-state col-major in SMEM.
// ============================================================================
#define GRU_HP 68                                   // h col-major row pitch
#define GRU_SMEM ((128 * 384 + 128 * GRU_HP + 64) * 4)

__global__ void __launch_bounds__(512, 1)
gru_kernel(const float* __restrict__ z, const int* __restrict__ x_in,
           const float* __restrict__ fc_w, const float* __restrict__ fc_b,
           const float* __restrict__ whh, const float* __restrict__ bhh)
{
    extern __shared__ float sm[];
    float* wT   = sm;                               // [128 k][384 g]
    float* h_s  = sm + 128 * 384;                   // [128 dim][GRU_HP rows]
    int*   tok_s = (int*)(h_s + 128 * GRU_HP);      // [64]

    const int tid = threadIdx.x;
    const int j = tid & 127;                        // gate column
    const int rowbase = (tid >> 7) * 16;            // warp-uniform
    const int bbase = blockIdx.x * 64;

    float hold[16];

    // ---- prologue: h0 = tanh(z @ fc_w^T + fc_b); stage in wT region ----
    {
        float* fwT = wT;                            // [64 k][129 j]
        float* z_s = wT + 64 * 129;                 // [64 r][64 k]
        for (int idx = tid; idx < 128 * 64; idx += 512) {
            int jj = idx >> 6, kk = idx & 63;
            fwT[kk * 129 + jj] = fc_w[idx];
        }
        for (int idx = tid; idx < 64 * 64; idx += 512) {
            int r = idx >> 6, k = idx & 63;
            z_s[idx] = z[(long)(bbase + r) * 64 + k];
        }
        __syncthreads();
        float acc[16];
        #pragma unroll
        for (int rr = 0; rr < 16; rr++) acc[rr] = 0.f;
        for (int k = 0; k < 64; k++) {
            float w = fwT[k * 129 + j];
            #pragma unroll
            for (int rr = 0; rr < 16; rr++)
                acc[rr] += z_s[(rowbase + rr) * 64 + k] * w;
        }
        float b = fc_b[j];
        #pragma unroll
        for (int rr = 0; rr < 16; rr++) {
            hold[rr] = ftanh(acc[rr] + b);
            h_s[j * GRU_HP + rowbase + rr] = hold[rr];
        }
        __syncthreads();
    }

    // ---- load Whh transposed: wT[k][g] = whh[g][k] ----
    for (int idx = tid; idx < 384 * 128; idx += 512) {
        int g = idx >> 7, k = idx & 127;
        wT[k * 384 + g] = whh[idx];
    }
    const float br = bhh[j], bz = bhh[128 + j], bn = bhh[256 + j];
    __syncthreads();

    // ---- 26 recurrent steps ----
    for (int t = 0; t < T_; t++) {
        if (tid < 64) tok_s[tid] = x_in[(long)(bbase + tid) * T_ + t];
        __syncthreads();                            // tok + previous h stores visible

        u64 ar[8], az[8], an[8];
        #pragma unroll
        for (int p = 0; p < 8; p++) { ar[p] = 0ull; az[p] = 0ull; an[p] = 0ull; }

        #pragma unroll 2
        for (int k = 0; k < 128; k++) {
            const float* wk = wT + k * 384 + j;
            u64 wr = f2_dup(wk[0]);
            u64 wz = f2_dup(wk[128]);
            u64 wn = f2_dup(wk[256]);
            const uint4* hp4 = (const uint4*)(h_s + k * GRU_HP + rowbase);
            #pragma unroll
            for (int q = 0; q < 4; q++) {
                uint4 hq = hp4[q];
                u64 h0 = f2_make(hq.x, hq.y);
                u64 h1 = f2_make(hq.z, hq.w);
                ffma2(ar[2*q],   h0, wr); ffma2(az[2*q],   h0, wz); ffma2(an[2*q],   h0, wn);
                ffma2(ar[2*q+1], h1, wr); ffma2(az[2*q+1], h1, wz); ffma2(an[2*q+1], h1, wn);
            }
        }

        float hnew[16];
        #pragma unroll
        for (int p = 0; p < 8; p++) {
            float arl, arh, azl, azh, anl, anh;
            f2_unpack(ar[p], arl, arh);
            f2_unpack(az[p], azl, azh);
            f2_unpack(an[p], anl, anh);
            int r0 = rowbase + 2 * p;
            const float* tb0 = g_table + tok_s[r0] * 384 + j;
            const float* tb1 = g_table + tok_s[r0 + 1] * 384 + j;

            float rg = fsigmoid(tb0[0]   + arl + br);
            float zg = fsigmoid(tb0[128] + azl + bz);
            float ng = ftanh   (tb0[256] + rg * (anl + bn));
            float h0n = (1.f - zg) * ng + zg * hold[2*p];

            float rg1 = fsigmoid(tb1[0]   + arh + br);
            float zg1 = fsigmoid(tb1[128] + azh + bz);
            float ng1 = ftanh   (tb1[256] + rg1 * (anh + bn));
            float h1n = (1.f - zg1) * ng1 + zg1 * hold[2*p+1];

            g_ygru[((long)(bbase + r0) * T_ + t) * 128 + j] = h0n;
            g_ygru[((long)(bbase + r0 + 1) * T_ + t) * 128 + j] = h1n;
            hnew[2*p] = h0n; hnew[2*p+1] = h1n;
        }
        __syncthreads();                            // all reads of h(t-1) done
        #pragma unroll
        for (int q = 0; q < 4; q++) {
            *(float4*)(h_s + j * GRU_HP + rowbase + 4 * q) = *(float4*)(hnew + 4 * q);
            hold[4*q] = hnew[4*q]; hold[4*q+1] = hnew[4*q+1];
            hold[4*q+2] = hnew[4*q+2]; hold[4*q+3] = hnew[4*q+3];
        }
        // next iteration's top sync publishes the stores
    }
}

// ============================================================================
// K3: xg = Y(B*T,128) @ lstm_wih^T(128,400) + (bih+bhh) — f32x2 GEMM
//   block: 64 rows x 400 cols. Thread: 4 rows x 7 column-pairs (64-col groups).
// ============================================================================
#define XG_SMEM ((128 * 400 + 64 * 64 + 448) * 4)

__global__ void __launch_bounds__(512, 1)
xg_kernel(const float* __restrict__ wih, const float* __restrict__ bih,
          const float* __restrict__ bhh)
{
    extern __shared__ float sm[];
    float* wT  = sm;                               // [128 k][400 c]
    float* y_s = sm + 128 * 400;                   // [64 r][64 k-chunk]
    float* bs  = y_s + 64 * 64;                    // [448]

    const int tid = threadIdx.x;
    const int tx = tid & 31;
    const int ty = tid >> 5;                       // 0..15 -> 4 rows each

    for (int idx = tid; idx < 400 * 128; idx += 512) {
        int c = idx / 128, k = idx & 127;
        wT[k * 400 + c] = wih[idx];
    }
    if (tid < 448) bs[tid] = (tid < 400) ? (bih[tid] + bhh[tid]) : 0.f;
    __syncthreads();

    u64 acc[4][7];
    #pragma unroll
    for (int q = 0; q < 4; q++)
        #pragma unroll
        for (int g = 0; g < 7; g++) acc[q][g] = 0ull;

    const long rbase = (long)blockIdx.x * 64;
    const int c0 = 2 * tx;                         // base column pair
    const bool g6ok = (tx < 8);                    // col 384+2tx < 400

    for (int kc = 0; kc < 2; kc++) {
        for (int idx = tid; idx < 64 * 64; idx += 512) {
            int r = idx >> 6, k = idx & 63;
            y_s[idx] = g_ygru[(rbase + r) * 128 + kc * 64 + k];
        }
        __syncthreads();
        #pragma unroll 2
        for (int kk = 0; kk < 64; kk++) {
            const float* wrow = wT + (kc * 64 + kk) * 400 + c0;
            u64 w[7];
            #pragma unroll
            for (int g = 0; g < 6; g++) w[g] = *(const u64*)(wrow + g * 64);
            w[6] = g6ok ? *(const u64*)(wrow + 384) : 0ull;
            #pragma unroll
            for (int q = 0; q < 4; q++) {
                u64 yq = f2_dup(y_s[(ty * 4 + q) * 64 + kk]);
                #pragma unroll
                for (int g = 0; g < 7; g++) ffma2(acc[q][g], yq, w[g]);
            }
        }
        __syncthreads();
    }

    #pragma unroll
    for (int q = 0; q < 4; q++) {
        long row = rbase + ty * 4 + q;
        #pragma unroll
        for (int g = 0; g < 7; g++) {
            int c = g * 64 + c0;
            if (c < 400) {
                float lo, hi;
                f2_unpack(acc[q][g], lo, hi);
                float2 o = make_float2(lo + bs[c], hi + bs[c + 1]);
                *(float2*)(g_xg + row * 400 + c) = o;
            }
        }
    }
}

// ============================================================================
// K4: LSTM (hidden=100) + fused logits (V=23), f32x2.
//   512 threads; j = tid&127 (active<100), 16 rows/thread; h col-major.
// ============================================================================
#define LS_HP 68
#define LS_SMEM ((100 * 400 + 100 * LS_HP + 100 * 24 + 24) * 4)

__global__ void __launch_bounds__(512, 1)
lstm_kernel(const float* __restrict__ whh, const float* __restrict__ ow,
            const float* __restrict__ ob, float* __restrict__ out)
{
    extern __shared__ float sm[];
    float* wT   = sm;                              // [100 k][400 c]
    float* h_s  = sm + 100 * 400;                  // [100 dim][LS_HP rows]
    float* ow_t = h_s + 100 * LS_HP;               // [100 e][24 v]
    float* ob_s = ow_t + 100 * 24;                 // [24]

    const int tid = threadIdx.x;
    const int j = tid & 127;
    const bool act = j < 100;
    const int rowbase = (tid >> 7) * 16;           // warp-uniform
    const int bbase = blockIdx.x * 64;

    for (int idx = tid; idx < 400 * 100; idx += 512) {
        int c = idx / 100, k = idx - c * 100;
        wT[k * 400 + c] = whh[idx];
    }
    for (int idx = tid; idx < 100 * 24; idx += 512) {
        int e = idx / 24, v = idx - e * 24;
        ow_t[idx] = (v < 23) ? ow[v * 100 + e] : 0.f;
    }
    if (tid < 24) ob_s[tid] = (tid < 23) ? ob[tid] : 0.f;
    for (int idx = tid; idx < 100 * LS_HP; idx += 512) h_s[idx] = 0.f;

    float c_reg[16];
    #pragma unroll
    for (int rr = 0; rr < 16; rr++) c_reg[rr] = 0.f;
    __syncthreads();

    for (int t = 0; t < T_; t++) {
        float hnew[16];

        if (act) {
            u64 ai[8], af[8], ag[8], ao[8];
            #pragma unroll
            for (int p = 0; p < 8; p++) { ai[p]=0ull; af[p]=0ull; ag[p]=0ull; ao[p]=0ull; }

            #pragma unroll 2
            for (int k = 0; k < 100; k++) {
                const float* wk = wT + k * 400 + j;
                u64 wi = f2_dup(wk[0]);
                u64 wf = f2_dup(wk[100]);
                u64 wg = f2_dup(wk[200]);
                u64 wo = f2_dup(wk[300]);
                const uint4* hp4 = (const uint4*)(h_s + k * LS_HP + rowbase);
                #pragma unroll
                for (int q = 0; q < 4; q++) {
                    uint4 hq = hp4[q];
                    u64 h0 = f2_make(hq.x, hq.y);
                    u64 h1 = f2_make(hq.z, hq.w);
                    ffma2(ai[2*q],   h0, wi); ffma2(af[2*q],   h0, wf);
                    ffma2(ag[2*q],   h0, wg); ffma2(ao[2*q],   h0, wo);
                    ffma2(ai[2*q+1], h1, wi); ffma2(af[2*q+1], h1, wf);
                    ffma2(ag[2*q+1], h1, wg); ffma2(ao[2*q+1], h1, wo);
                }
            }

            #pragma unroll
            for (int p = 0; p < 8; p++) {
                float il, ih, fl, fh, gl, gh, ol, oh;
                f2_unpack(ai[p], il, ih); f2_unpack(af[p], fl, fh);
                f2_unpack(ag[p], gl, gh); f2_unpack(ao[p], ol, oh);
                int r0 = rowbase + 2 * p;
                const float* x0 = g_xg + ((long)(bbase + r0) * T_ + t) * 400 + j;
                const float* x1 = g_xg + ((long)(bbase + r0 + 1) * T_ + t) * 400 + j;

                float c0 = fsigmoid(x0[100] + fl) * c_reg[2*p]
                         + fsigmoid(x0[0]   + il) * ftanh(x0[200] + gl);
                hnew[2*p] = fsigmoid(x0[300] + ol) * ftanh(c0);
                c_reg[2*p] = c0;

                float c1 = fsigmoid(x1[100] + fh) * c_reg[2*p+1]
                         + fsigmoid(x1[0]   + ih) * ftanh(x1[200] + gh);
                hnew[2*p+1] = fsigmoid(x1[300] + oh) * ftanh(c1);
                c_reg[2*p+1] = c1;
            }
        }
        __syncthreads();                           // all reads of h(t-1) done
        if (act) {
            #pragma unroll
            for (int q = 0; q < 4; q++)
                *(float4*)(h_s + j * LS_HP + rowbase + 4 * q) = *(float4*)(hnew + 4 * q);
        }
        __syncthreads();                           // h(t) visible

        // fused logits: 64 rows x 12 v-pairs = 768 items; packed over v
        #pragma unroll
        for (int it = tid; it < 768; it += 512) {
            int row = it / 12;
            int vp = it - row * 12;
            int v = 2 * vp;
            u64 acc = *(const u64*)(ob_s + v);
            const float* hr = h_s + row;
            const float* owp = ow_t + v;
            #pragma unroll 4
            for (int e = 0; e < E_; e++) {
                u64 hp = f2_dup(hr[e * LS_HP]);
                ffma2(acc, hp, *(const u64*)(owp + e * 24));
            }
            float lo, hi;
            f2_unpack(acc, lo, hi);
            float* op = out + ((long)(bbase + row) * T_ + t) * V_ + v;
            op[0] = lo;
            if (v + 1 < V_) op[1] = hi;
        }
        __syncthreads();                           // logits reads done before next store
    }
}

// ============================================================================
// launch
// ============================================================================
extern "C" void kernel_launch(void* const* d_in, const int* in_sizes, int n_in,
                              void* d_out, int out_size) {
    const float* z     = (const float*)d_in[0];
    const int*   x_in  = (const int*)  d_in[1];
    const float* emb   = (const float*)d_in[2];
    const float* fc_w  = (const float*)d_in[3];
    const float* fc_b  = (const float*)d_in[4];
    const float* gwih  = (const float*)d_in[5];
    const float* gwhh  = (const float*)d_in[6];
    const float* gbih  = (const float*)d_in[7];
    const float* gbhh  = (const float*)d_in[8];
    const float* lwih  = (const float*)d_in[9];
    const float* lwhh  = (const float*)d_in[10];
    const float* lbih  = (const float*)d_in[11];
    const float* lbhh  = (const float*)d_in[12];
    const float* out_w = (const float*)d_in[13];
    const float* out_b = (const float*)d_in[14];
    float* out = (float*)d_out;

    cudaFuncSetAttribute(gru_kernel,  cudaFuncAttributeMaxDynamicSharedMemorySize, GRU_SMEM);
    cudaFuncSetAttribute(xg_kernel,   cudaFuncAttributeMaxDynamicSharedMemorySize, XG_SMEM);
    cudaFuncSetAttribute(lstm_kernel, cudaFuncAttributeMaxDynamicSharedMemorySize, LS_SMEM);

    table_kernel<<<V_, 384>>>(emb, gwih, gbih);
    gru_kernel<<<B_ / 64, 512, GRU_SMEM>>>(z, x_in, fc_w, fc_b, gwhh, gbhh);
    xg_kernel<<<(B_ * T_) / 64, 512, XG_SMEM>>>(lwih, lbih, lbhh);
    lstm_kernel<<<B_ / 64, 512, LS_SMEM>>>(lwhh, out_w, out_b, out);
}

// round 14
// speedup vs baseline: 1.0399x; 1.0001x over previous
#include <cuda_runtime.h>

// Problem dims (fixed by the dataset)
#define B_ 8192
#define T_ 26
#define V_ 23
#define E_ 100
#define H_ 128
#define L_ 64

typedef unsigned long long u64;

// -------- device scratch (static allocation: allowed; no cudaMalloc) --------
__device__ float g_table[V_ * 3 * H_];                  // 23 x 384 : emb@Wih^T + bih
__device__ float g_ygru[(long)B_ * T_ * H_];            // ~109 MB
__device__ float g_xg[(long)B_ * T_ * 4 * E_];          // ~341 MB

__device__ __forceinline__ float fsigmoid(float x) {
    return __fdividef(1.0f, 1.0f + __expf(-x));
}
__device__ __forceinline__ float ftanh(float x) {
    return 1.0f - __fdividef(2.0f, __expf(2.0f * x) + 1.0f);
}

// ---- packed f32x2 helpers (Blackwell FFMA2 path) ----
__device__ __forceinline__ void ffma2(u64& d, u64 a, u64 b) {
    asm("fma.rn.f32x2 %0, %1, %2, %0;" : "+l"(d) : "l"(a), "l"(b));
}
__device__ __forceinline__ u64 f2_dup(float x) {
    unsigned int u = __float_as_uint(x);
    u64 r; asm("mov.b64 %0, {%1, %1};" : "=l"(r) : "r"(u)); return r;
}
__device__ __forceinline__ u64 f2_make(unsigned int lo, unsigned int hi) {
    u64 r; asm("mov.b64 %0, {%1, %2};" : "=l"(r) : "r"(lo), "r"(hi)); return r;
}
__device__ __forceinline__ void f2_unpack(u64 v, float& lo, float& hi) {
    unsigned int a, b;
    asm("mov.b64 {%0, %1}, %2;" : "=r"(a), "=r"(b) : "l"(v));
    lo = __uint_as_float(a); hi = __uint_as_float(b);
}

// ============================================================================
// K1: table[v][g] = sum_e emb[v][e]*gru_wih[g][e] + gru_bih[g]
// ============================================================================
__global__ void table_kernel(const float* __restrict__ emb,
                             const float* __restrict__ wih,
                             const float* __restrict__ bih) {
    __shared__ float e_s[E_];
    int v = blockIdx.x;
    if (threadIdx.x < E_) e_s[threadIdx.x] = emb[v * E_ + threadIdx.x];
    __syncthreads();
    int g = threadIdx.x;                 // 0..383
    float acc = bih[g];
    #pragma unroll 4
    for (int e = 0; e < E_; e++) acc += e_s[e] * wih[g * E_ + e];
    g_table[v * 384 + g] = acc;
}

// ============================================================================
// K2: GRU, f32x2. One block = 64 rows, all 26 steps. h-state col-major in SMEM.
// ============================================================================
#define GRU_HP 68                                   // h col-major row pitch
#define GRU_SMEM ((128 * 384 + 128 * GRU_HP + 64) * 4)

__global__ void __launch_bounds__(512, 1)
gru_kernel(const float* __restrict__ z, const int* __restrict__ x_in,
           const float* __restrict__ fc_w, const float* __restrict__ fc_b,
           const float* __restrict__ whh, const float* __restrict__ bhh)
{
    extern __shared__ float sm[];
    float* wT   = sm;                               // [128 k][384 g]
    float* h_s  = sm + 128 * 384;                   // [128 dim][GRU_HP rows]
    int*   tok_s = (int*)(h_s + 128 * GRU_HP);      // [64]

    const int tid = threadIdx.x;
    const int j = tid & 127;                        // gate column
    const int rowbase = (tid >> 7) * 16;            // warp-uniform
    const int bbase = blockIdx.x * 64;

    float hold[16];

    // ---- prologue: h0 = tanh(z @ fc_w^T + fc_b); stage in wT region ----
    {
        float* fwT = wT;                            // [64 k][129 j]
        float* z_s = wT + 64 * 129;                 // [64 r][64 k]
        for (int idx = tid; idx < 128 * 64; idx += 512) {
            int jj = idx >> 6, kk = idx & 63;
            fwT[kk * 129 + jj] = fc_w[idx];
        }
        for (int idx = tid; idx < 64 * 64; idx += 512) {
            int r = idx >> 6, k = idx & 63;
            z_s[idx] = z[(long)(bbase + r) * 64 + k];
        }
        __syncthreads();
        float acc[16];
        #pragma unroll
        for (int rr = 0; rr < 16; rr++) acc[rr] = 0.f;
        for (int k = 0; k < 64; k++) {
            float w = fwT[k * 129 + j];
            #pragma unroll
            for (int rr = 0; rr < 16; rr++)
                acc[rr] += z_s[(rowbase + rr) * 64 + k] * w;
        }
        float b = fc_b[j];
        #pragma unroll
        for (int rr = 0; rr < 16; rr++) {
            hold[rr] = ftanh(acc[rr] + b);
            h_s[j * GRU_HP + rowbase + rr] = hold[rr];
        }
        __syncthreads();
    }

    // ---- load Whh transposed: wT[k][g] = whh[g][k] ----
    for (int idx = tid; idx < 384 * 128; idx += 512) {
        int g = idx >> 7, k = idx & 127;
        wT[k * 384 + g] = whh[idx];
    }
    const float br = bhh[j], bz = bhh[128 + j], bn = bhh[256 + j];
    __syncthreads();

    // ---- 26 recurrent steps ----
    for (int t = 0; t < T_; t++) {
        if (tid < 64) tok_s[tid] = x_in[(long)(bbase + tid) * T_ + t];
        __syncthreads();                            // tok + previous h stores visible

        u64 ar[8], az[8], an[8];
        #pragma unroll
        for (int p = 0; p < 8; p++) { ar[p] = 0ull; az[p] = 0ull; an[p] = 0ull; }

        #pragma unroll 2
        for (int k = 0; k < 128; k++) {
            const float* wk = wT + k * 384 + j;
            u64 wr = f2_dup(wk[0]);
            u64 wz = f2_dup(wk[128]);
            u64 wn = f2_dup(wk[256]);
            const uint4* hp4 = (const uint4*)(h_s + k * GRU_HP + rowbase);
            #pragma unroll
            for (int q = 0; q < 4; q++) {
                uint4 hq = hp4[q];
                u64 h0 = f2_make(hq.x, hq.y);
                u64 h1 = f2_make(hq.z, hq.w);
                ffma2(ar[2*q],   h0, wr); ffma2(az[2*q],   h0, wz); ffma2(an[2*q],   h0, wn);
                ffma2(ar[2*q+1], h1, wr); ffma2(az[2*q+1], h1, wz); ffma2(an[2*q+1], h1, wn);
            }
        }

        float hnew[16];
        #pragma unroll
        for (int p = 0; p < 8; p++) {
            float arl, arh, azl, azh, anl, anh;
            f2_unpack(ar[p], arl, arh);
            f2_unpack(az[p], azl, azh);
            f2_unpack(an[p], anl, anh);
            int r0 = rowbase + 2 * p;
            const float* tb0 = g_table + tok_s[r0] * 384 + j;
            const float* tb1 = g_table + tok_s[r0 + 1] * 384 + j;

            float rg = fsigmoid(tb0[0]   + arl + br);
            float zg = fsigmoid(tb0[128] + azl + bz);
            float ng = ftanh   (tb0[256] + rg * (anl + bn));
            float h0n = (1.f - zg) * ng + zg * hold[2*p];

            float rg1 = fsigmoid(tb1[0]   + arh + br);
            float zg1 = fsigmoid(tb1[128] + azh + bz);
            float ng1 = ftanh   (tb1[256] + rg1 * (anh + bn));
            float h1n = (1.f - zg1) * ng1 + zg1 * hold[2*p+1];

            g_ygru[((long)(bbase + r0) * T_ + t) * 128 + j] = h0n;
            g_ygru[((long)(bbase + r0 + 1) * T_ + t) * 128 + j] = h1n;
            hnew[2*p] = h0n; hnew[2*p+1] = h1n;
        }
        __syncthreads();                            // all reads of h(t-1) done
        #pragma unroll
        for (int q = 0; q < 4; q++) {
            *(float4*)(h_s + j * GRU_HP + rowbase + 4 * q) = *(float4*)(hnew + 4 * q);
            hold[4*q] = hnew[4*q]; hold[4*q+1] = hnew[4*q+1];
            hold[4*q+2] = hnew[4*q+2]; hold[4*q+3] = hnew[4*q+3];
        }
        // next iteration's top sync publishes the stores
    }
}

// ============================================================================
// K3: xg = Y(B*T,128) @ lstm_wih^T(128,400) + (bih+bhh) — f32x2 GEMM
//   block: 64 rows x 400 cols. Thread: 4 rows x 7 column-pairs (64-col groups).
// ============================================================================
#define XG_SMEM ((128 * 400 + 64 * 64 + 448) * 4)

__global__ void __launch_bounds__(512, 1)
xg_kernel(const float* __restrict__ wih, const float* __restrict__ bih,
          const float* __restrict__ bhh)
{
    extern __shared__ float sm[];
    float* wT  = sm;                               // [128 k][400 c]
    float* y_s = sm + 128 * 400;                   // [64 r][64 k-chunk]
    float* bs  = y_s + 64 * 64;                    // [448]

    const int tid = threadIdx.x;
    const int tx = tid & 31;
    const int ty = tid >> 5;                       // 0..15 -> 4 rows each

    for (int idx = tid; idx < 400 * 128; idx += 512) {
        int c = idx / 128, k = idx & 127;
        wT[k * 400 + c] = wih[idx];
    }
    if (tid < 448) bs[tid] = (tid < 400) ? (bih[tid] + bhh[tid]) : 0.f;
    __syncthreads();

    u64 acc[4][7];
    #pragma unroll
    for (int q = 0; q < 4; q++)
        #pragma unroll
        for (int g = 0; g < 7; g++) acc[q][g] = 0ull;

    const long rbase = (long)blockIdx.x * 64;
    const int c0 = 2 * tx;                         // base column pair
    const bool g6ok = (tx < 8);                    // col 384+2tx < 400

    for (int kc = 0; kc < 2; kc++) {
        for (int idx = tid; idx < 64 * 64; idx += 512) {
            int r = idx >> 6, k = idx & 63;
            y_s[idx] = g_ygru[(rbase + r) * 128 + kc * 64 + k];
        }
        __syncthreads();
        #pragma unroll 2
        for (int kk = 0; kk < 64; kk++) {
            const float* wrow = wT + (kc * 64 + kk) * 400 + c0;
            u64 w[7];
            #pragma unroll
            for (int g = 0; g < 6; g++) w[g] = *(const u64*)(wrow + g * 64);
            w[6] = g6ok ? *(const u64*)(wrow + 384) : 0ull;
            #pragma unroll
            for (int q = 0; q < 4; q++) {
                u64 yq = f2_dup(y_s[(ty * 4 + q) * 64 + kk]);
                #pragma unroll
                for (int g = 0; g < 7; g++) ffma2(acc[q][g], yq, w[g]);
            }
        }
        __syncthreads();
    }

    #pragma unroll
    for (int q = 0; q < 4; q++) {
        long row = rbase + ty * 4 + q;
        #pragma unroll
        for (int g = 0; g < 7; g++) {
            int c = g * 64 + c0;
            if (c < 400) {
                float lo, hi;
                f2_unpack(acc[q][g], lo, hi);
                float2 o = make_float2(lo + bs[c], hi + bs[c + 1]);
                *(float2*)(g_xg + row * 400 + c) = o;
            }
        }
    }
}

// ============================================================================
// K4: LSTM (hidden=100) + fused logits (V=23), f32x2.
//   512 threads; j = tid&127 (active<100), 16 rows/thread; h col-major.
// ============================================================================
#define LS_HP 68
#define LS_SMEM ((100 * 400 + 100 * LS_HP + 100 * 24 + 24) * 4)

__global__ void __launch_bounds__(512, 1)
lstm_kernel(const float* __restrict__ whh, const float* __restrict__ ow,
            const float* __restrict__ ob, float* __restrict__ out)
{
    extern __shared__ float sm[];
    float* wT   = sm;                              // [100 k][400 c]
    float* h_s  = sm + 100 * 400;                  // [100 dim][LS_HP rows]
    float* ow_t = h_s + 100 * LS_HP;               // [100 e][24 v]
    float* ob_s = ow_t + 100 * 24;                 // [24]

    const int tid = threadIdx.x;
    const int j = tid & 127;
    const bool act = j < 100;
    const int rowbase = (tid >> 7) * 16;           // warp-uniform
    const int bbase = blockIdx.x * 64;

    for (int idx = tid; idx < 400 * 100; idx += 512) {
        int c = idx / 100, k = idx - c * 100;
        wT[k * 400 + c] = whh[idx];
    }
    for (int idx = tid; idx < 100 * 24; idx += 512) {
        int e = idx / 24, v = idx - e * 24;
        ow_t[idx] = (v < 23) ? ow[v * 100 + e] : 0.f;
    }
    if (tid < 24) ob_s[tid] = (tid < 23) ? ob[tid] : 0.f;
    for (int idx = tid; idx < 100 * LS_HP; idx += 512) h_s[idx] = 0.f;

    float c_reg[16];
    #pragma unroll
    for (int rr = 0; rr < 16; rr++) c_reg[rr] = 0.f;
    __syncthreads();

    for (int t = 0; t < T_; t++) {
        float hnew[16];

        if (act) {
            u64 ai[8], af[8], ag[8], ao[8];
            #pragma unroll
            for (int p = 0; p < 8; p++) { ai[p]=0ull; af[p]=0ull; ag[p]=0ull; ao[p]=0ull; }

            #pragma unroll 2
            for (int k = 0; k < 100; k++) {
                const float* wk = wT + k * 400 + j;
                u64 wi = f2_dup(wk[0]);
                u64 wf = f2_dup(wk[100]);
                u64 wg = f2_dup(wk[200]);
                u64 wo = f2_dup(wk[300]);
                const uint4* hp4 = (const uint4*)(h_s + k * LS_HP + rowbase);
                #pragma unroll
                for (int q = 0; q < 4; q++) {
                    uint4 hq = hp4[q];
                    u64 h0 = f2_make(hq.x, hq.y);
                    u64 h1 = f2_make(hq.z, hq.w);
                    ffma2(ai[2*q],   h0, wi); ffma2(af[2*q],   h0, wf);
                    ffma2(ag[2*q],   h0, wg); ffma2(ao[2*q],   h0, wo);
                    ffma2(ai[2*q+1], h1, wi); ffma2(af[2*q+1], h1, wf);
                    ffma2(ag[2*q+1], h1, wg); ffma2(ao[2*q+1], h1, wo);
                }
            }

            #pragma unroll
            for (int p = 0; p < 8; p++) {
                float il, ih, fl, fh, gl, gh, ol, oh;
                f2_unpack(ai[p], il, ih); f2_unpack(af[p], fl, fh);
                f2_unpack(ag[p], gl, gh); f2_unpack(ao[p], ol, oh);
                int r0 = rowbase + 2 * p;
                const float* x0 = g_xg + ((long)(bbase + r0) * T_ + t) * 400 + j;
                const float* x1 = g_xg + ((long)(bbase + r0 + 1) * T_ + t) * 400 + j;

                float c0 = fsigmoid(x0[100] + fl) * c_reg[2*p]
                         + fsigmoid(x0[0]   + il) * ftanh(x0[200] + gl);
                hnew[2*p] = fsigmoid(x0[300] + ol) * ftanh(c0);
                c_reg[2*p] = c0;

                float c1 = fsigmoid(x1[100] + fh) * c_reg[2*p+1]
                         + fsigmoid(x1[0]   + ih) * ftanh(x1[200] + gh);
                hnew[2*p+1] = fsigmoid(x1[300] + oh) * ftanh(c1);
                c_reg[2*p+1] = c1;
            }
        }
        __syncthreads();                           // all reads of h(t-1) done
        if (act) {
            #pragma unroll
            for (int q = 0; q < 4; q++)
                *(float4*)(h_s + j * LS_HP + rowbase + 4 * q) = *(float4*)(hnew + 4 * q);
        }
        __syncthreads();                           // h(t) visible

        // fused logits: 64 rows x 12 v-pairs = 768 items; packed over v
        #pragma unroll
        for (int it = tid; it < 768; it += 512) {
            int row = it / 12;
            int vp = it - row * 12;
            int v = 2 * vp;
            u64 acc = *(const u64*)(ob_s + v);
            const float* hr = h_s + row;
            const float* owp = ow_t + v;
            #pragma unroll 4
            for (int e = 0; e < E_; e++) {
                u64 hp = f2_dup(hr[e * LS_HP]);
                ffma2(acc, hp, *(const u64*)(owp + e * 24));
            }
            float lo, hi;
            f2_unpack(acc, lo, hi);
            float* op = out + ((long)(bbase + row) * T_ + t) * V_ + v;
            op[0] = lo;
            if (v + 1 < V_) op[1] = hi;
        }
        __syncthreads();                           // logits reads done before next store
    }
}

// ============================================================================
// launch
// ============================================================================
extern "C" void kernel_launch(void* const* d_in, const int* in_sizes, int n_in,
                              void* d_out, int out_size) {
    const float* z     = (const float*)d_in[0];
    const int*   x_in  = (const int*)  d_in[1];
    const float* emb   = (const float*)d_in[2];
    const float* fc_w  = (const float*)d_in[3];
    const float* fc_b  = (const float*)d_in[4];
    const float* gwih  = (const float*)d_in[5];
    const float* gwhh  = (const float*)d_in[6];
    const float* gbih  = (const float*)d_in[7];
    const float* gbhh  = (const float*)d_in[8];
    const float* lwih  = (const float*)d_in[9];
    const float* lwhh  = (const float*)d_in[10];
    const float* lbih  = (const float*)d_in[11];
    const float* lbhh  = (const float*)d_in[12];
    const float* out_w = (const float*)d_in[13];
    const float* out_b = (const float*)d_in[14];
    float* out = (float*)d_out;

    cudaFuncSetAttribute(gru_kernel,  cudaFuncAttributeMaxDynamicSharedMemorySize, GRU_SMEM);
    cudaFuncSetAttribute(xg_kernel,   cudaFuncAttributeMaxDynamicSharedMemorySize, XG_SMEM);
    cudaFuncSetAttribute(lstm_kernel, cudaFuncAttributeMaxDynamicSharedMemorySize, LS_SMEM);

    table_kernel<<<V_, 384>>>(emb, gwih, gbih);
    gru_kernel<<<B_ / 64, 512, GRU_SMEM>>>(z, x_in, fc_w, fc_b, gwhh, gbhh);
    xg_kernel<<<(B_ * T_) / 64, 512, XG_SMEM>>>(lwih, lbih, lbhh);
    lstm_kernel<<<B_ / 64, 512, LS_SMEM>>>(lwhh, out_w, out_b, out);
}